// round 13
// baseline (speedup 1.0000x reference)
#include <cuda_runtime.h>
#include <cuda_fp16.h>
#include <math.h>

#define NN 100000
#define EE 1600000
#define EP (EE + NN)
#define HH 4
#define CC 32
#define DD 128
#define GG 64
#define LL 4
#define IN_DIM 7
#define NEG_SLOPE 0.2f

// ---------------- scratch ----------------
__device__ float  g_h[NN * DD];     // residual stream (fp32)
__device__ __half g_hp[NN * DD];    // projected features (fp16)
__device__ float  g_asrc[NN * HH];
__device__ float  g_adst[NN * HH];
__device__ int    g_cnt[NN];
__device__ int    g_off[NN + 1];
__device__ int    g_rank[EP];       // rank of edge within its dst segment
__device__ int    g_csr[EP];        // src node per edge, grouped by dst
__device__ float  g_gsum[GG * DD];
__device__ float  g_gcnt[GG];

__device__ __forceinline__ float lrelu(float x) { return x > 0.0f ? x : NEG_SLOPE * x; }
__device__ __forceinline__ float elu(float x)   { return x > 0.0f ? x : expm1f(x); }
__device__ __forceinline__ unsigned f2tf32(float f) {
    unsigned u;
    asm("cvt.rna.tf32.f32 %0, %1;" : "=r"(u) : "f"(f));
    return u;
}

// ================= CSR build (once per call; dst layout layer-invariant) ====
__global__ void csr_hist_kernel(const int* __restrict__ dst) {
    int e = blockIdx.x * blockDim.x + threadIdx.x;
    if (e < EP) {
        int d = (e < EE) ? dst[e] : (e - EE);
        g_rank[e] = atomicAdd(&g_cnt[d], 1);
    }
}

__global__ void csr_scan_kernel() {
    __shared__ int sh[1024];
    const int chunk = (NN + 1023) / 1024;
    int t = threadIdx.x;
    int b = t * chunk;
    int e = b + chunk; if (e > NN) e = NN;
    int s = 0;
    for (int i = b; i < e; i++) s += g_cnt[i];
    sh[t] = s;
    __syncthreads();
    for (int o = 1; o < 1024; o <<= 1) {
        int v = (t >= o) ? sh[t - o] : 0;
        __syncthreads();
        sh[t] += v;
        __syncthreads();
    }
    int run = (t == 0) ? 0 : sh[t - 1];
    for (int i = b; i < e; i++) {
        g_off[i] = run;
        run += g_cnt[i];
    }
    if (t == 1023) g_off[NN] = run;
}

// atomic-free: position = off[d] + precomputed rank
__global__ void csr_scatter_kernel(const int* __restrict__ src, const int* __restrict__ dst) {
    int e = blockIdx.x * blockDim.x + threadIdx.x;
    if (e < EP) {
        int s, d;
        if (e < EE) { s = src[e]; d = dst[e]; } else { s = d = e - EE; }
        g_csr[g_off[d] + g_rank[e]] = s;
    }
}

// ================= layer-0 GEMM + alpha (warp per node) =================
__global__ __launch_bounds__(256) void gemm0_kernel(
    const float* __restrict__ x, const float* __restrict__ W0,
    const float* __restrict__ a_src, const float* __restrict__ a_dst)
{
    __shared__ float4 s_W[IN_DIM * 32];
    __shared__ float4 s_as[32], s_ad[32];
    if (threadIdx.x < IN_DIM * 32) s_W[threadIdx.x] = ((const float4*)W0)[threadIdx.x];
    if (threadIdx.x < 32) {
        s_as[threadIdx.x] = ((const float4*)a_src)[threadIdx.x];
        s_ad[threadIdx.x] = ((const float4*)a_dst)[threadIdx.x];
    }
    __syncthreads();
    int lane = threadIdx.x & 31;
    int wid = (blockIdx.x * blockDim.x + threadIdx.x) >> 5;
    int tw = (gridDim.x * blockDim.x) >> 5;
    for (int n = wid; n < NN; n += tw) {
        float xr[IN_DIM];
        #pragma unroll
        for (int k = 0; k < IN_DIM; k++) xr[k] = __ldg(&x[n * IN_DIM + k]);
        float4 acc = {0, 0, 0, 0};
        #pragma unroll
        for (int k = 0; k < IN_DIM; k++) {
            float4 wv = s_W[k * 32 + lane];
            acc.x += xr[k] * wv.x;
            acc.y += xr[k] * wv.y;
            acc.z += xr[k] * wv.z;
            acc.w += xr[k] * wv.w;
        }
        ((__half2*)g_hp)[(size_t)n * 64 + lane * 2]     = __floats2half2_rn(acc.x, acc.y);
        ((__half2*)g_hp)[(size_t)n * 64 + lane * 2 + 1] = __floats2half2_rn(acc.z, acc.w);
        float4 a = s_as[lane], b = s_ad[lane];
        float ps = acc.x * a.x + acc.y * a.y + acc.z * a.z + acc.w * a.w;
        float pd = acc.x * b.x + acc.y * b.y + acc.z * b.z + acc.w * b.w;
        #pragma unroll
        for (int o = 4; o > 0; o >>= 1) {
            ps += __shfl_down_sync(0xFFFFFFFFu, ps, o, 8);
            pd += __shfl_down_sync(0xFFFFFFFFu, pd, o, 8);
        }
        if ((lane & 7) == 0) {
            int h = lane >> 3;
            g_asrc[n * HH + h] = ps;
            g_adst[n * HH + h] = pd;
        }
    }
}

// ================= hidden GEMM (TF32 mma, double-buffered) + alpha ==========
#define HS_STRIDE 20
#define WS_STRIDE 136
__global__ __launch_bounds__(256) void gemmH_mma_kernel(
    const float* __restrict__ Wg,
    const float* __restrict__ a_src, const float* __restrict__ a_dst)
{
    __shared__ unsigned Hs[2][128 * HS_STRIDE];
    __shared__ unsigned Wsm[2][16 * WS_STRIDE];
    __shared__ float sA[DD], sB[DD];

    int t = threadIdx.x;
    int lane = t & 31;
    int w = t >> 5;
    int gid = lane >> 2;
    int tg = lane & 3;
    int n0 = blockIdx.x * 128;
    int m0 = w * 16;

    if (t < DD) { sA[t] = a_src[t]; sB[t] = a_dst[t]; }

    float acc[16][4];
    #pragma unroll
    for (int nt = 0; nt < 16; nt++)
        #pragma unroll
        for (int q = 0; q < 4; q++) acc[nt][q] = 0.0f;

    auto load_tile = [&](int kt, int buf) {
        #pragma unroll
        for (int it = 0; it < 2; it++) {
            int idx = t + it * 256;
            int r = idx >> 2, q = idx & 3;
            float4 v = {0, 0, 0, 0};
            if (n0 + r < NN) v = ((const float4*)g_h)[(size_t)(n0 + r) * 32 + kt * 4 + q];
            unsigned* p = &Hs[buf][r * HS_STRIDE + q * 4];
            p[0] = f2tf32(v.x); p[1] = f2tf32(v.y); p[2] = f2tf32(v.z); p[3] = f2tf32(v.w);
        }
        #pragma unroll
        for (int it = 0; it < 2; it++) {
            int idx = t + it * 256;
            int r = idx >> 5, q = idx & 31;
            float4 v = ((const float4*)Wg)[(kt * 16 + r) * 32 + q];
            unsigned* p = &Wsm[buf][r * WS_STRIDE + q * 4];
            p[0] = f2tf32(v.x); p[1] = f2tf32(v.y); p[2] = f2tf32(v.z); p[3] = f2tf32(v.w);
        }
    };

    load_tile(0, 0);
    __syncthreads();

    for (int kt = 0; kt < 8; kt++) {
        int cur = kt & 1;
        if (kt < 7) load_tile(kt + 1, cur ^ 1);

        #pragma unroll
        for (int kk = 0; kk < 2; kk++) {
            unsigned a0 = Hs[cur][(m0 + gid) * HS_STRIDE + kk * 8 + tg];
            unsigned a1 = Hs[cur][(m0 + gid + 8) * HS_STRIDE + kk * 8 + tg];
            unsigned a2 = Hs[cur][(m0 + gid) * HS_STRIDE + kk * 8 + tg + 4];
            unsigned a3 = Hs[cur][(m0 + gid + 8) * HS_STRIDE + kk * 8 + tg + 4];
            #pragma unroll
            for (int nt = 0; nt < 16; nt++) {
                unsigned b0 = Wsm[cur][(kk * 8 + tg) * WS_STRIDE + nt * 8 + gid];
                unsigned b1 = Wsm[cur][(kk * 8 + tg + 4) * WS_STRIDE + nt * 8 + gid];
                asm volatile(
                    "mma.sync.aligned.m16n8k8.row.col.f32.tf32.tf32.f32 "
                    "{%0,%1,%2,%3}, {%4,%5,%6,%7}, {%8,%9}, {%0,%1,%2,%3};"
                    : "+f"(acc[nt][0]), "+f"(acc[nt][1]), "+f"(acc[nt][2]), "+f"(acc[nt][3])
                    : "r"(a0), "r"(a1), "r"(a2), "r"(a3), "r"(b0), "r"(b1));
            }
        }
        __syncthreads();
    }

    int na = n0 + m0 + gid;
    int nb = na + 8;
    #pragma unroll
    for (int nt = 0; nt < 16; nt++) {
        if (na < NN) ((__half2*)g_hp)[(size_t)na * 64 + nt * 4 + tg] = __floats2half2_rn(acc[nt][0], acc[nt][1]);
        if (nb < NN) ((__half2*)g_hp)[(size_t)nb * 64 + nt * 4 + tg] = __floats2half2_rn(acc[nt][2], acc[nt][3]);
    }
    float psa[4] = {0, 0, 0, 0}, pda[4] = {0, 0, 0, 0};
    float psb[4] = {0, 0, 0, 0}, pdb[4] = {0, 0, 0, 0};
    #pragma unroll
    for (int nt = 0; nt < 16; nt++) {
        int h = nt >> 2;
        int ch = nt * 8 + 2 * tg;
        float s0 = sA[ch], s1 = sA[ch + 1];
        float d0 = sB[ch], d1 = sB[ch + 1];
        psa[h] += acc[nt][0] * s0 + acc[nt][1] * s1;
        pda[h] += acc[nt][0] * d0 + acc[nt][1] * d1;
        psb[h] += acc[nt][2] * s0 + acc[nt][3] * s1;
        pdb[h] += acc[nt][2] * d0 + acc[nt][3] * d1;
    }
    #pragma unroll
    for (int h = 0; h < 4; h++) {
        #pragma unroll
        for (int o = 1; o < 4; o <<= 1) {
            psa[h] += __shfl_xor_sync(0xFFFFFFFFu, psa[h], o);
            pda[h] += __shfl_xor_sync(0xFFFFFFFFu, pda[h], o);
            psb[h] += __shfl_xor_sync(0xFFFFFFFFu, psb[h], o);
            pdb[h] += __shfl_xor_sync(0xFFFFFFFFu, pdb[h], o);
        }
    }
    if (tg == 0) {
        if (na < NN) {
            float4 v = {psa[0], psa[1], psa[2], psa[3]};
            ((float4*)g_asrc)[na] = v;
            float4 u = {pda[0], pda[1], pda[2], pda[3]};
            ((float4*)g_adst)[na] = u;
        }
        if (nb < NN) {
            float4 v = {psb[0], psb[1], psb[2], psb[3]};
            ((float4*)g_asrc)[nb] = v;
            float4 u = {pdb[0], pdb[1], pdb[2], pdb[3]};
            ((float4*)g_adst)[nb] = u;
        }
    }
}

// ================= fused one-pass edge aggregation + LN + ELU + residual ====
// warp per dst node; lane owns channels [lane*4, lane*4+4); head = lane>>3.
// Chunk-PAIR main loop: 16 gathers in flight per warp; then one single-chunk
// step; then the <8-edge tail.
__global__ __launch_bounds__(256) void fused_edge_kernel(
    const float* __restrict__ bias,
    const float* __restrict__ lng, const float* __restrict__ lnb,
    int is_first, int is_last, float* __restrict__ outp)
{
    int lane = threadIdx.x & 31;
    int h = lane >> 3;
    int wid = (blockIdx.x * blockDim.x + threadIdx.x) >> 5;
    int tw = (gridDim.x * blockDim.x) >> 5;
    int grp = lane & 24;
    int j8 = lane & 7;
    const uint2* hp2 = (const uint2*)g_hp;

    for (int d = wid; d < NN; d += tw) {
        int beg = g_off[d], end = g_off[d + 1];
        float4 ad4 = ((const float4*)g_adst)[d];
        float adh = (h == 0) ? ad4.x : (h == 1) ? ad4.y : (h == 2) ? ad4.z : ad4.w;

        // pipeline heads for chunk A (c) and chunk B (c+8)
        int iA = beg + j8;
        int sA_ = 0; float aA = 0.0f;
        if (iA < end) { sA_ = __ldg(&g_csr[iA]); aA = __ldg(&g_asrc[sA_ * HH + h]); }
        int iB = beg + 8 + j8;
        int sB_ = 0; float aB = 0.0f;
        if (iB < end) { sB_ = __ldg(&g_csr[iB]); aB = __ldg(&g_asrc[sB_ * HH + h]); }

        float z = 0.0f;
        float4 acc = {0, 0, 0, 0};
        int c = beg;

        // ---- pair loop: 16 valid edges, 16 gathers in flight ----
        for (; c + 16 <= end; c += 16) {
            int inA = c + 16 + j8;
            int snA = 0; float anA = 0.0f;
            if (inA < end) { snA = __ldg(&g_csr[inA]); anA = __ldg(&g_asrc[snA * HH + h]); }
            int inB = c + 24 + j8;
            int snB = 0; float anB = 0.0f;
            if (inB < end) { snB = __ldg(&g_csr[inB]); anB = __ldg(&g_asrc[snB * HH + h]); }

            float eA = __expf(fminf(lrelu(aA + adh), 60.0f));
            float eB = __expf(fminf(lrelu(aB + adh), 60.0f));
            z += eA + eB;
            #pragma unroll
            for (int j = 0; j < 8; j++) {
                int sj   = __shfl_sync(0xFFFFFFFFu, sA_, grp | j);
                float ej = __shfl_sync(0xFFFFFFFFu, eA, grp | j);
                uint2 hv = __ldg(&hp2[(size_t)sj * 32 + lane]);
                float2 f01 = __half22float2(*reinterpret_cast<const __half2*>(&hv.x));
                float2 f23 = __half22float2(*reinterpret_cast<const __half2*>(&hv.y));
                acc.x += ej * f01.x; acc.y += ej * f01.y;
                acc.z += ej * f23.x; acc.w += ej * f23.y;
            }
            #pragma unroll
            for (int j = 0; j < 8; j++) {
                int sj   = __shfl_sync(0xFFFFFFFFu, sB_, grp | j);
                float ej = __shfl_sync(0xFFFFFFFFu, eB, grp | j);
                uint2 hv = __ldg(&hp2[(size_t)sj * 32 + lane]);
                float2 f01 = __half22float2(*reinterpret_cast<const __half2*>(&hv.x));
                float2 f23 = __half22float2(*reinterpret_cast<const __half2*>(&hv.y));
                acc.x += ej * f01.x; acc.y += ej * f01.y;
                acc.z += ej * f23.x; acc.w += ej * f23.y;
            }
            sA_ = snA; aA = anA;
            sB_ = snB; aB = anB;
        }

        // ---- one full chunk if >= 8 edges remain ----
        if (c + 8 <= end) {
            float eA = __expf(fminf(lrelu(aA + adh), 60.0f));
            z += eA;
            #pragma unroll
            for (int j = 0; j < 8; j++) {
                int sj   = __shfl_sync(0xFFFFFFFFu, sA_, grp | j);
                float ej = __shfl_sync(0xFFFFFFFFu, eA, grp | j);
                uint2 hv = __ldg(&hp2[(size_t)sj * 32 + lane]);
                float2 f01 = __half22float2(*reinterpret_cast<const __half2*>(&hv.x));
                float2 f23 = __half22float2(*reinterpret_cast<const __half2*>(&hv.y));
                acc.x += ej * f01.x; acc.y += ej * f01.y;
                acc.z += ej * f23.x; acc.w += ej * f23.y;
            }
            c += 8;
            sA_ = sB_; aA = aB;
        }

        // ---- tail: < 8 edges ----
        int lim = end - c;
        if (lim > 0) {
            float e_own = 0.0f;
            if (j8 < lim) e_own = __expf(fminf(lrelu(aA + adh), 60.0f));
            z += e_own;
            for (int j = 0; j < lim; j++) {
                int sj   = __shfl_sync(0xFFFFFFFFu, sA_, grp | j);
                float ej = __shfl_sync(0xFFFFFFFFu, e_own, grp | j);
                uint2 hv = __ldg(&hp2[(size_t)sj * 32 + lane]);
                float2 f01 = __half22float2(*reinterpret_cast<const __half2*>(&hv.x));
                float2 f23 = __half22float2(*reinterpret_cast<const __half2*>(&hv.y));
                acc.x += ej * f01.x; acc.y += ej * f01.y;
                acc.z += ej * f23.x; acc.w += ej * f23.y;
            }
        }

        #pragma unroll
        for (int o = 4; o > 0; o >>= 1) z += __shfl_xor_sync(0xFFFFFFFFu, z, o, 8);
        float inv = 1.0f / (z + 1e-16f);

        float4 b4 = ((const float4*)bias)[lane];
        float4 v;
        v.x = acc.x * inv + b4.x;
        v.y = acc.y * inv + b4.y;
        v.z = acc.z * inv + b4.z;
        v.w = acc.w * inv + b4.w;

        float s  = v.x + v.y + v.z + v.w;
        float sq = v.x * v.x + v.y * v.y + v.z * v.z + v.w * v.w;
        #pragma unroll
        for (int o = 16; o > 0; o >>= 1) {
            s  += __shfl_xor_sync(0xFFFFFFFFu, s, o);
            sq += __shfl_xor_sync(0xFFFFFFFFu, sq, o);
        }
        float mu = s * (1.0f / 128.0f);
        float var = sq * (1.0f / 128.0f) - mu * mu;
        float rs = rsqrtf(var + 1e-5f);
        float4 gv = ((const float4*)lng)[lane];
        float4 bv = ((const float4*)lnb)[lane];
        float4 r;
        r.x = elu((v.x - mu) * rs * gv.x + bv.x);
        r.y = elu((v.y - mu) * rs * gv.y + bv.y);
        r.z = elu((v.z - mu) * rs * gv.z + bv.z);
        r.w = elu((v.w - mu) * rs * gv.w + bv.w);
        if (!is_first) {
            float4 hold = ((const float4*)g_h)[(size_t)d * 32 + lane];
            r.x += hold.x; r.y += hold.y; r.z += hold.z; r.w += hold.w;
        }
        ((float4*)g_h)[(size_t)d * 32 + lane] = r;
        if (is_last) ((float4*)outp)[(size_t)d * 32 + lane] = r;
    }
}

// ================= graph pooling =================
__global__ void pool_cnt_kernel(const int* __restrict__ batch) {
    __shared__ float c[GG];
    if (threadIdx.x < GG) c[threadIdx.x] = 0.0f;
    __syncthreads();
    int tid = blockIdx.x * blockDim.x + threadIdx.x;
    int stride = gridDim.x * blockDim.x;
    for (int n = tid; n < NN; n += stride) atomicAdd(&c[batch[n]], 1.0f);
    __syncthreads();
    if (threadIdx.x < GG && c[threadIdx.x] != 0.0f)
        atomicAdd(&g_gcnt[threadIdx.x], c[threadIdx.x]);
}

#define NPB 128
__global__ void pool_acc_kernel(const int* __restrict__ batch) {
    int j = threadIdx.x;
    int n0 = blockIdx.x * NPB;
    int n1 = n0 + NPB; if (n1 > NN) n1 = NN;
    if (n0 >= NN) return;
    int gcur = batch[n0];
    float acc = 0.0f;
    for (int n = n0; n < n1; n++) {
        int g = batch[n];
        if (g != gcur) {
            atomicAdd(&g_gsum[gcur * DD + j], acc);
            acc = 0.0f;
            gcur = g;
        }
        acc += g_h[(size_t)n * DD + j];
    }
    atomicAdd(&g_gsum[gcur * DD + j], acc);
}

__global__ void pool_fin_kernel(float* __restrict__ outp) {
    int i = blockIdx.x * blockDim.x + threadIdx.x;
    if (i < GG * DD) {
        int g = i >> 7;
        outp[NN * DD + i] = g_gsum[i] / fmaxf(g_gcnt[g], 1.0f);
    }
}

// ================= launch =================
extern "C" void kernel_launch(void* const* d_in, const int* in_sizes, int n_in,
                              void* d_out, int out_size) {
    const float* x      = (const float*)d_in[0];
    const int*   ei     = (const int*)  d_in[1];
    const int*   batch  = (const int*)  d_in[2];
    const float* W0     = (const float*)d_in[3];
    const float* a_src0 = (const float*)d_in[4];
    const float* a_dst0 = (const float*)d_in[5];
    const float* b0     = (const float*)d_in[6];
    const float* Ws     = (const float*)d_in[7];
    const float* a_srcs = (const float*)d_in[8];
    const float* a_dsts = (const float*)d_in[9];
    const float* bs     = (const float*)d_in[10];
    const float* ln_g   = (const float*)d_in[11];
    const float* ln_b   = (const float*)d_in[12];
    float* out = (float*)d_out;

    const int* srcp = ei;
    const int* dstp = ei + EE;

    void* p_cnt = nullptr;  cudaGetSymbolAddress(&p_cnt,  g_cnt);
    void* p_gsum = nullptr; cudaGetSymbolAddress(&p_gsum, g_gsum);
    void* p_gcnt = nullptr; cudaGetSymbolAddress(&p_gcnt, g_gcnt);
    cudaMemsetAsync(p_cnt, 0, NN * sizeof(int));
    cudaMemsetAsync(p_gsum, 0, GG * DD * sizeof(float));
    cudaMemsetAsync(p_gcnt, 0, GG * sizeof(float));

    csr_hist_kernel<<<(EP + 255) / 256, 256>>>(dstp);
    csr_scan_kernel<<<1, 1024>>>();
    csr_scatter_kernel<<<(EP + 255) / 256, 256>>>(srcp, dstp);

    for (int l = 0; l < LL; l++) {
        const float* asr  = (l == 0) ? a_src0 : (a_srcs + (l - 1) * HH * CC);
        const float* ads  = (l == 0) ? a_dst0 : (a_dsts + (l - 1) * HH * CC);
        const float* bias = (l == 0) ? b0     : (bs + (l - 1) * DD);

        if (l == 0)
            gemm0_kernel<<<1024, 256>>>(x, W0, asr, ads);
        else
            gemmH_mma_kernel<<<(NN + 127) / 128, 256>>>(Ws + (l - 1) * DD * DD, asr, ads);

        fused_edge_kernel<<<2048, 256>>>(bias, ln_g + l * DD, ln_b + l * DD,
                                         (l == 0) ? 1 : 0, (l == LL - 1) ? 1 : 0, out);
    }

    pool_cnt_kernel<<<256, 256>>>(batch);
    pool_acc_kernel<<<(NN + NPB - 1) / NPB, 128>>>(batch);
    pool_fin_kernel<<<(GG * DD + 255) / 256, 256>>>(out);
}

// round 14
// speedup vs baseline: 1.0657x; 1.0657x over previous
#include <cuda_runtime.h>
#include <cuda_fp16.h>
#include <math.h>

#define NN 100000
#define EE 1600000
#define EP (EE + NN)
#define HH 4
#define CC 32
#define DD 128
#define GG 64
#define LL 4
#define IN_DIM 7
#define NEG_SLOPE 0.2f

// ---------------- scratch ----------------
__device__ float  g_h[NN * DD];     // residual stream (fp32)
__device__ __half g_hp[NN * DD];    // projected features (fp16)
__device__ float  g_asrc[NN * HH];
__device__ float  g_adst[NN * HH];
__device__ int    g_cnt[NN];
__device__ int    g_off[NN + 1];
__device__ int    g_rank[EP];       // rank of edge within its dst segment
__device__ int    g_csr[EP];        // src node per edge, grouped by dst
__device__ float  g_gsum[GG * DD];
__device__ float  g_gcnt[GG];

__device__ __forceinline__ float lrelu(float x) { return x > 0.0f ? x : NEG_SLOPE * x; }
__device__ __forceinline__ float elu(float x)   { return x > 0.0f ? x : expm1f(x); }
__device__ __forceinline__ unsigned f2tf32(float f) {
    unsigned u;
    asm("cvt.rna.tf32.f32 %0, %1;" : "=r"(u) : "f"(f));
    return u;
}

// ================= CSR build (once per call; dst layout layer-invariant) ====
__global__ void csr_hist_kernel(const int* __restrict__ dst) {
    int e = blockIdx.x * blockDim.x + threadIdx.x;
    if (e < EP) {
        int d = (e < EE) ? dst[e] : (e - EE);
        g_rank[e] = atomicAdd(&g_cnt[d], 1);
    }
}

__global__ void csr_scan_kernel() {
    __shared__ int sh[1024];
    const int chunk = (NN + 1023) / 1024;
    int t = threadIdx.x;
    int b = t * chunk;
    int e = b + chunk; if (e > NN) e = NN;
    int s = 0;
    for (int i = b; i < e; i++) s += g_cnt[i];
    sh[t] = s;
    __syncthreads();
    for (int o = 1; o < 1024; o <<= 1) {
        int v = (t >= o) ? sh[t - o] : 0;
        __syncthreads();
        sh[t] += v;
        __syncthreads();
    }
    int run = (t == 0) ? 0 : sh[t - 1];
    for (int i = b; i < e; i++) {
        g_off[i] = run;
        run += g_cnt[i];
    }
    if (t == 1023) g_off[NN] = run;
}

// atomic-free: position = off[d] + precomputed rank
__global__ void csr_scatter_kernel(const int* __restrict__ src, const int* __restrict__ dst) {
    int e = blockIdx.x * blockDim.x + threadIdx.x;
    if (e < EP) {
        int s, d;
        if (e < EE) { s = src[e]; d = dst[e]; } else { s = d = e - EE; }
        g_csr[g_off[d] + g_rank[e]] = s;
    }
}

// ================= layer-0 GEMM + alpha (warp per node) =================
__global__ __launch_bounds__(256) void gemm0_kernel(
    const float* __restrict__ x, const float* __restrict__ W0,
    const float* __restrict__ a_src, const float* __restrict__ a_dst)
{
    __shared__ float4 s_W[IN_DIM * 32];
    __shared__ float4 s_as[32], s_ad[32];
    if (threadIdx.x < IN_DIM * 32) s_W[threadIdx.x] = ((const float4*)W0)[threadIdx.x];
    if (threadIdx.x < 32) {
        s_as[threadIdx.x] = ((const float4*)a_src)[threadIdx.x];
        s_ad[threadIdx.x] = ((const float4*)a_dst)[threadIdx.x];
    }
    __syncthreads();
    int lane = threadIdx.x & 31;
    int wid = (blockIdx.x * blockDim.x + threadIdx.x) >> 5;
    int tw = (gridDim.x * blockDim.x) >> 5;
    for (int n = wid; n < NN; n += tw) {
        float xr[IN_DIM];
        #pragma unroll
        for (int k = 0; k < IN_DIM; k++) xr[k] = __ldg(&x[n * IN_DIM + k]);
        float4 acc = {0, 0, 0, 0};
        #pragma unroll
        for (int k = 0; k < IN_DIM; k++) {
            float4 wv = s_W[k * 32 + lane];
            acc.x += xr[k] * wv.x;
            acc.y += xr[k] * wv.y;
            acc.z += xr[k] * wv.z;
            acc.w += xr[k] * wv.w;
        }
        ((__half2*)g_hp)[(size_t)n * 64 + lane * 2]     = __floats2half2_rn(acc.x, acc.y);
        ((__half2*)g_hp)[(size_t)n * 64 + lane * 2 + 1] = __floats2half2_rn(acc.z, acc.w);
        float4 a = s_as[lane], b = s_ad[lane];
        float ps = acc.x * a.x + acc.y * a.y + acc.z * a.z + acc.w * a.w;
        float pd = acc.x * b.x + acc.y * b.y + acc.z * b.z + acc.w * b.w;
        #pragma unroll
        for (int o = 4; o > 0; o >>= 1) {
            ps += __shfl_down_sync(0xFFFFFFFFu, ps, o, 8);
            pd += __shfl_down_sync(0xFFFFFFFFu, pd, o, 8);
        }
        if ((lane & 7) == 0) {
            int h = lane >> 3;
            g_asrc[n * HH + h] = ps;
            g_adst[n * HH + h] = pd;
        }
    }
}

// ================= hidden GEMM (TF32 mma, double-buffered) + alpha ==========
#define HS_STRIDE 20
#define WS_STRIDE 136
__global__ __launch_bounds__(256) void gemmH_mma_kernel(
    const float* __restrict__ Wg,
    const float* __restrict__ a_src, const float* __restrict__ a_dst)
{
    __shared__ unsigned Hs[2][128 * HS_STRIDE];
    __shared__ unsigned Wsm[2][16 * WS_STRIDE];
    __shared__ float sA[DD], sB[DD];

    int t = threadIdx.x;
    int lane = t & 31;
    int w = t >> 5;
    int gid = lane >> 2;
    int tg = lane & 3;
    int n0 = blockIdx.x * 128;
    int m0 = w * 16;

    if (t < DD) { sA[t] = a_src[t]; sB[t] = a_dst[t]; }

    float acc[16][4];
    #pragma unroll
    for (int nt = 0; nt < 16; nt++)
        #pragma unroll
        for (int q = 0; q < 4; q++) acc[nt][q] = 0.0f;

    auto load_tile = [&](int kt, int buf) {
        #pragma unroll
        for (int it = 0; it < 2; it++) {
            int idx = t + it * 256;
            int r = idx >> 2, q = idx & 3;
            float4 v = {0, 0, 0, 0};
            if (n0 + r < NN) v = ((const float4*)g_h)[(size_t)(n0 + r) * 32 + kt * 4 + q];
            unsigned* p = &Hs[buf][r * HS_STRIDE + q * 4];
            p[0] = f2tf32(v.x); p[1] = f2tf32(v.y); p[2] = f2tf32(v.z); p[3] = f2tf32(v.w);
        }
        #pragma unroll
        for (int it = 0; it < 2; it++) {
            int idx = t + it * 256;
            int r = idx >> 5, q = idx & 31;
            float4 v = ((const float4*)Wg)[(kt * 16 + r) * 32 + q];
            unsigned* p = &Wsm[buf][r * WS_STRIDE + q * 4];
            p[0] = f2tf32(v.x); p[1] = f2tf32(v.y); p[2] = f2tf32(v.z); p[3] = f2tf32(v.w);
        }
    };

    load_tile(0, 0);
    __syncthreads();

    for (int kt = 0; kt < 8; kt++) {
        int cur = kt & 1;
        if (kt < 7) load_tile(kt + 1, cur ^ 1);

        #pragma unroll
        for (int kk = 0; kk < 2; kk++) {
            unsigned a0 = Hs[cur][(m0 + gid) * HS_STRIDE + kk * 8 + tg];
            unsigned a1 = Hs[cur][(m0 + gid + 8) * HS_STRIDE + kk * 8 + tg];
            unsigned a2 = Hs[cur][(m0 + gid) * HS_STRIDE + kk * 8 + tg + 4];
            unsigned a3 = Hs[cur][(m0 + gid + 8) * HS_STRIDE + kk * 8 + tg + 4];
            #pragma unroll
            for (int nt = 0; nt < 16; nt++) {
                unsigned b0 = Wsm[cur][(kk * 8 + tg) * WS_STRIDE + nt * 8 + gid];
                unsigned b1 = Wsm[cur][(kk * 8 + tg + 4) * WS_STRIDE + nt * 8 + gid];
                asm volatile(
                    "mma.sync.aligned.m16n8k8.row.col.f32.tf32.tf32.f32 "
                    "{%0,%1,%2,%3}, {%4,%5,%6,%7}, {%8,%9}, {%0,%1,%2,%3};"
                    : "+f"(acc[nt][0]), "+f"(acc[nt][1]), "+f"(acc[nt][2]), "+f"(acc[nt][3])
                    : "r"(a0), "r"(a1), "r"(a2), "r"(a3), "r"(b0), "r"(b1));
            }
        }
        __syncthreads();
    }

    int na = n0 + m0 + gid;
    int nb = na + 8;
    #pragma unroll
    for (int nt = 0; nt < 16; nt++) {
        if (na < NN) ((__half2*)g_hp)[(size_t)na * 64 + nt * 4 + tg] = __floats2half2_rn(acc[nt][0], acc[nt][1]);
        if (nb < NN) ((__half2*)g_hp)[(size_t)nb * 64 + nt * 4 + tg] = __floats2half2_rn(acc[nt][2], acc[nt][3]);
    }
    float psa[4] = {0, 0, 0, 0}, pda[4] = {0, 0, 0, 0};
    float psb[4] = {0, 0, 0, 0}, pdb[4] = {0, 0, 0, 0};
    #pragma unroll
    for (int nt = 0; nt < 16; nt++) {
        int h = nt >> 2;
        int ch = nt * 8 + 2 * tg;
        float s0 = sA[ch], s1 = sA[ch + 1];
        float d0 = sB[ch], d1 = sB[ch + 1];
        psa[h] += acc[nt][0] * s0 + acc[nt][1] * s1;
        pda[h] += acc[nt][0] * d0 + acc[nt][1] * d1;
        psb[h] += acc[nt][2] * s0 + acc[nt][3] * s1;
        pdb[h] += acc[nt][2] * d0 + acc[nt][3] * d1;
    }
    #pragma unroll
    for (int h = 0; h < 4; h++) {
        #pragma unroll
        for (int o = 1; o < 4; o <<= 1) {
            psa[h] += __shfl_xor_sync(0xFFFFFFFFu, psa[h], o);
            pda[h] += __shfl_xor_sync(0xFFFFFFFFu, pda[h], o);
            psb[h] += __shfl_xor_sync(0xFFFFFFFFu, psb[h], o);
            pdb[h] += __shfl_xor_sync(0xFFFFFFFFu, pdb[h], o);
        }
    }
    if (tg == 0) {
        if (na < NN) {
            float4 v = {psa[0], psa[1], psa[2], psa[3]};
            ((float4*)g_asrc)[na] = v;
            float4 u = {pda[0], pda[1], pda[2], pda[3]};
            ((float4*)g_adst)[na] = u;
        }
        if (nb < NN) {
            float4 v = {psb[0], psb[1], psb[2], psb[3]};
            ((float4*)g_asrc)[nb] = v;
            float4 u = {pdb[0], pdb[1], pdb[2], pdb[3]};
            ((float4*)g_adst)[nb] = u;
        }
    }
}

// ================= fused one-pass edge aggregation + LN + ELU + residual ====
// warp per dst node; lane owns channels [lane*4, lane*4+4); head = lane>>3.
// Full chunks take the unrolled path (8 gathers in flight). (R12 version.)
__global__ __launch_bounds__(256) void fused_edge_kernel(
    const float* __restrict__ bias,
    const float* __restrict__ lng, const float* __restrict__ lnb,
    int is_first, int is_last, float* __restrict__ outp)
{
    int lane = threadIdx.x & 31;
    int h = lane >> 3;
    int wid = (blockIdx.x * blockDim.x + threadIdx.x) >> 5;
    int tw = (gridDim.x * blockDim.x) >> 5;
    int grp = lane & 24;
    int j8 = lane & 7;
    const uint2* hp2 = (const uint2*)g_hp;

    for (int d = wid; d < NN; d += tw) {
        int beg = g_off[d], end = g_off[d + 1];
        float4 ad4 = ((const float4*)g_adst)[d];
        float adh = (h == 0) ? ad4.x : (h == 1) ? ad4.y : (h == 2) ? ad4.z : ad4.w;

        int i0 = beg + j8;
        int s_cur = 0; float as_cur = 0.0f;
        if (i0 < end) {
            s_cur = __ldg(&g_csr[i0]);
            as_cur = __ldg(&g_asrc[s_cur * HH + h]);
        }

        float z = 0.0f;
        float4 acc = {0, 0, 0, 0};
        int c = beg;
        for (; c + 8 <= end; c += 8) {
            int inx = c + 8 + j8;
            int s_nxt = 0; float as_nxt = 0.0f;
            if (inx < end) {
                s_nxt = __ldg(&g_csr[inx]);
                as_nxt = __ldg(&g_asrc[s_nxt * HH + h]);
            }
            float e_own = __expf(fminf(lrelu(as_cur + adh), 60.0f));
            z += e_own;
            #pragma unroll
            for (int j = 0; j < 8; j++) {
                int sj   = __shfl_sync(0xFFFFFFFFu, s_cur, grp | j);
                float ej = __shfl_sync(0xFFFFFFFFu, e_own, grp | j);
                uint2 hv = __ldg(&hp2[(size_t)sj * 32 + lane]);
                float2 f01 = __half22float2(*reinterpret_cast<const __half2*>(&hv.x));
                float2 f23 = __half22float2(*reinterpret_cast<const __half2*>(&hv.y));
                acc.x += ej * f01.x;
                acc.y += ej * f01.y;
                acc.z += ej * f23.x;
                acc.w += ej * f23.y;
            }
            s_cur = s_nxt; as_cur = as_nxt;
        }
        int lim = end - c;
        if (lim > 0) {
            float e_own = 0.0f;
            if (j8 < lim) e_own = __expf(fminf(lrelu(as_cur + adh), 60.0f));
            z += e_own;
            for (int j = 0; j < lim; j++) {
                int sj   = __shfl_sync(0xFFFFFFFFu, s_cur, grp | j);
                float ej = __shfl_sync(0xFFFFFFFFu, e_own, grp | j);
                uint2 hv = __ldg(&hp2[(size_t)sj * 32 + lane]);
                float2 f01 = __half22float2(*reinterpret_cast<const __half2*>(&hv.x));
                float2 f23 = __half22float2(*reinterpret_cast<const __half2*>(&hv.y));
                acc.x += ej * f01.x;
                acc.y += ej * f01.y;
                acc.z += ej * f23.x;
                acc.w += ej * f23.y;
            }
        }

        #pragma unroll
        for (int o = 4; o > 0; o >>= 1) z += __shfl_xor_sync(0xFFFFFFFFu, z, o, 8);
        float inv = 1.0f / (z + 1e-16f);

        float4 b4 = ((const float4*)bias)[lane];
        float4 v;
        v.x = acc.x * inv + b4.x;
        v.y = acc.y * inv + b4.y;
        v.z = acc.z * inv + b4.z;
        v.w = acc.w * inv + b4.w;

        float s  = v.x + v.y + v.z + v.w;
        float sq = v.x * v.x + v.y * v.y + v.z * v.z + v.w * v.w;
        #pragma unroll
        for (int o = 16; o > 0; o >>= 1) {
            s  += __shfl_xor_sync(0xFFFFFFFFu, s, o);
            sq += __shfl_xor_sync(0xFFFFFFFFu, sq, o);
        }
        float mu = s * (1.0f / 128.0f);
        float var = sq * (1.0f / 128.0f) - mu * mu;
        float rs = rsqrtf(var + 1e-5f);
        float4 gv = ((const float4*)lng)[lane];
        float4 bv = ((const float4*)lnb)[lane];
        float4 r;
        r.x = elu((v.x - mu) * rs * gv.x + bv.x);
        r.y = elu((v.y - mu) * rs * gv.y + bv.y);
        r.z = elu((v.z - mu) * rs * gv.z + bv.z);
        r.w = elu((v.w - mu) * rs * gv.w + bv.w);
        if (!is_first) {
            float4 hold = ((const float4*)g_h)[(size_t)d * 32 + lane];
            r.x += hold.x; r.y += hold.y; r.z += hold.z; r.w += hold.w;
        }
        ((float4*)g_h)[(size_t)d * 32 + lane] = r;
        if (is_last) ((float4*)outp)[(size_t)d * 32 + lane] = r;
    }
}

// ================= graph pooling =================
__global__ void pool_cnt_kernel(const int* __restrict__ batch) {
    __shared__ float c[GG];
    if (threadIdx.x < GG) c[threadIdx.x] = 0.0f;
    __syncthreads();
    int tid = blockIdx.x * blockDim.x + threadIdx.x;
    int stride = gridDim.x * blockDim.x;
    for (int n = tid; n < NN; n += stride) atomicAdd(&c[batch[n]], 1.0f);
    __syncthreads();
    if (threadIdx.x < GG && c[threadIdx.x] != 0.0f)
        atomicAdd(&g_gcnt[threadIdx.x], c[threadIdx.x]);
}

#define NPB 32
__global__ void pool_acc_kernel(const int* __restrict__ batch) {
    int j = threadIdx.x;
    int n0 = blockIdx.x * NPB;
    int n1 = n0 + NPB; if (n1 > NN) n1 = NN;
    if (n0 >= NN) return;
    int gcur = batch[n0];
    float acc = 0.0f;
    for (int n = n0; n < n1; n++) {
        int g = batch[n];
        if (g != gcur) {
            atomicAdd(&g_gsum[gcur * DD + j], acc);
            acc = 0.0f;
            gcur = g;
        }
        acc += g_h[(size_t)n * DD + j];
    }
    atomicAdd(&g_gsum[gcur * DD + j], acc);
}

__global__ void pool_fin_kernel(float* __restrict__ outp) {
    int i = blockIdx.x * blockDim.x + threadIdx.x;
    if (i < GG * DD) {
        int g = i >> 7;
        outp[NN * DD + i] = g_gsum[i] / fmaxf(g_gcnt[g], 1.0f);
    }
}

// ================= launch =================
extern "C" void kernel_launch(void* const* d_in, const int* in_sizes, int n_in,
                              void* d_out, int out_size) {
    const float* x      = (const float*)d_in[0];
    const int*   ei     = (const int*)  d_in[1];
    const int*   batch  = (const int*)  d_in[2];
    const float* W0     = (const float*)d_in[3];
    const float* a_src0 = (const float*)d_in[4];
    const float* a_dst0 = (const float*)d_in[5];
    const float* b0     = (const float*)d_in[6];
    const float* Ws     = (const float*)d_in[7];
    const float* a_srcs = (const float*)d_in[8];
    const float* a_dsts = (const float*)d_in[9];
    const float* bs     = (const float*)d_in[10];
    const float* ln_g   = (const float*)d_in[11];
    const float* ln_b   = (const float*)d_in[12];
    float* out = (float*)d_out;

    const int* srcp = ei;
    const int* dstp = ei + EE;

    void* p_cnt = nullptr;  cudaGetSymbolAddress(&p_cnt,  g_cnt);
    void* p_gsum = nullptr; cudaGetSymbolAddress(&p_gsum, g_gsum);
    void* p_gcnt = nullptr; cudaGetSymbolAddress(&p_gcnt, g_gcnt);
    cudaMemsetAsync(p_cnt, 0, NN * sizeof(int));
    cudaMemsetAsync(p_gsum, 0, GG * DD * sizeof(float));
    cudaMemsetAsync(p_gcnt, 0, GG * sizeof(float));

    csr_hist_kernel<<<(EP + 255) / 256, 256>>>(dstp);
    csr_scan_kernel<<<1, 1024>>>();
    csr_scatter_kernel<<<(EP + 255) / 256, 256>>>(srcp, dstp);

    for (int l = 0; l < LL; l++) {
        const float* asr  = (l == 0) ? a_src0 : (a_srcs + (l - 1) * HH * CC);
        const float* ads  = (l == 0) ? a_dst0 : (a_dsts + (l - 1) * HH * CC);
        const float* bias = (l == 0) ? b0     : (bs + (l - 1) * DD);

        if (l == 0)
            gemm0_kernel<<<1024, 256>>>(x, W0, asr, ads);
        else
            gemmH_mma_kernel<<<(NN + 127) / 128, 256>>>(Ws + (l - 1) * DD * DD, asr, ads);

        fused_edge_kernel<<<2048, 256>>>(bias, ln_g + l * DD, ln_b + l * DD,
                                         (l == 0) ? 1 : 0, (l == LL - 1) ? 1 : 0, out);
    }

    pool_cnt_kernel<<<256, 256>>>(batch);
    pool_acc_kernel<<<(NN + NPB - 1) / NPB, 128>>>(batch);
    pool_fin_kernel<<<(GG * DD + 255) / 256, 256>>>(out);
}

// round 16
// speedup vs baseline: 1.0891x; 1.0220x over previous
#include <cuda_runtime.h>
#include <cuda_fp16.h>
#include <math.h>

#define NN 100000
#define EE 1600000
#define EP (EE + NN)
#define HH 4
#define CC 32
#define DD 128
#define GG 64
#define LL 4
#define IN_DIM 7
#define NEG_SLOPE 0.2f

// ---------------- scratch ----------------
__device__ float  g_h[NN * DD];     // residual stream (fp32)
__device__ __half g_hp[NN * DD];    // projected features (fp16)
__device__ float  g_asrc[NN * HH];
__device__ float  g_adst[NN * HH];
__device__ int    g_cnt[NN];
__device__ int    g_off[NN + 1];
__device__ int    g_rank[EP];       // rank of edge within its dst segment
__device__ int    g_csr[EP];        // src node per edge, grouped by dst
__device__ float  g_gsum[GG * DD];
__device__ float  g_gcnt[GG];

__device__ __forceinline__ float lrelu(float x) { return x > 0.0f ? x : NEG_SLOPE * x; }
__device__ __forceinline__ float elu(float x)   { return x > 0.0f ? x : expm1f(x); }
__device__ __forceinline__ unsigned f2tf32(float f) {
    unsigned u;
    asm("cvt.rna.tf32.f32 %0, %1;" : "=r"(u) : "f"(f));
    return u;
}

// ================= CSR build (once per call; dst layout layer-invariant) ====
// 4 edges per thread via int4 loads.
__global__ void csr_hist_kernel(const int* __restrict__ dst) {
    int t = blockIdx.x * blockDim.x + threadIdx.x;
    int base = t * 4;
    if (base + 3 < EE) {
        int4 dd = __ldg(&((const int4*)dst)[t]);
        g_rank[base + 0] = atomicAdd(&g_cnt[dd.x], 1);
        g_rank[base + 1] = atomicAdd(&g_cnt[dd.y], 1);
        g_rank[base + 2] = atomicAdd(&g_cnt[dd.z], 1);
        g_rank[base + 3] = atomicAdd(&g_cnt[dd.w], 1);
    } else {
        for (int e = base; e < base + 4 && e < EP; e++) {
            int d = (e < EE) ? __ldg(&dst[e]) : (e - EE);
            g_rank[e] = atomicAdd(&g_cnt[d], 1);
        }
    }
}

__global__ void csr_scan_kernel() {
    __shared__ int sh[1024];
    const int chunk = (NN + 1023) / 1024;
    int t = threadIdx.x;
    int b = t * chunk;
    int e = b + chunk; if (e > NN) e = NN;
    int s = 0;
    for (int i = b; i < e; i++) s += g_cnt[i];
    sh[t] = s;
    __syncthreads();
    for (int o = 1; o < 1024; o <<= 1) {
        int v = (t >= o) ? sh[t - o] : 0;
        __syncthreads();
        sh[t] += v;
        __syncthreads();
    }
    int run = (t == 0) ? 0 : sh[t - 1];
    for (int i = b; i < e; i++) {
        g_off[i] = run;
        run += g_cnt[i];
    }
    if (t == 1023) g_off[NN] = run;
}

// atomic-free: position = off[d] + precomputed rank; 4 edges per thread
__global__ void csr_scatter_kernel(const int* __restrict__ src, const int* __restrict__ dst) {
    int t = blockIdx.x * blockDim.x + threadIdx.x;
    int base = t * 4;
    if (base + 3 < EE) {
        int4 dd = __ldg(&((const int4*)dst)[t]);
        int4 ss = __ldg(&((const int4*)src)[t]);
        int4 rr = *(&((const int4*)g_rank)[t]);
        g_csr[g_off[dd.x] + rr.x] = ss.x;
        g_csr[g_off[dd.y] + rr.y] = ss.y;
        g_csr[g_off[dd.z] + rr.z] = ss.z;
        g_csr[g_off[dd.w] + rr.w] = ss.w;
    } else {
        for (int e = base; e < base + 4 && e < EP; e++) {
            int s, d;
            if (e < EE) { s = __ldg(&src[e]); d = __ldg(&dst[e]); } else { s = d = e - EE; }
            g_csr[g_off[d] + g_rank[e]] = s;
        }
    }
}

// ================= layer-0 GEMM + alpha (warp per node) =================
__global__ __launch_bounds__(256) void gemm0_kernel(
    const float* __restrict__ x, const float* __restrict__ W0,
    const float* __restrict__ a_src, const float* __restrict__ a_dst)
{
    __shared__ float4 s_W[IN_DIM * 32];
    __shared__ float4 s_as[32], s_ad[32];
    if (threadIdx.x < IN_DIM * 32) s_W[threadIdx.x] = ((const float4*)W0)[threadIdx.x];
    if (threadIdx.x < 32) {
        s_as[threadIdx.x] = ((const float4*)a_src)[threadIdx.x];
        s_ad[threadIdx.x] = ((const float4*)a_dst)[threadIdx.x];
    }
    __syncthreads();
    int lane = threadIdx.x & 31;
    int wid = (blockIdx.x * blockDim.x + threadIdx.x) >> 5;
    int tw = (gridDim.x * blockDim.x) >> 5;
    for (int n = wid; n < NN; n += tw) {
        float xr[IN_DIM];
        #pragma unroll
        for (int k = 0; k < IN_DIM; k++) xr[k] = __ldg(&x[n * IN_DIM + k]);
        float4 acc = {0, 0, 0, 0};
        #pragma unroll
        for (int k = 0; k < IN_DIM; k++) {
            float4 wv = s_W[k * 32 + lane];
            acc.x += xr[k] * wv.x;
            acc.y += xr[k] * wv.y;
            acc.z += xr[k] * wv.z;
            acc.w += xr[k] * wv.w;
        }
        ((__half2*)g_hp)[(size_t)n * 64 + lane * 2]     = __floats2half2_rn(acc.x, acc.y);
        ((__half2*)g_hp)[(size_t)n * 64 + lane * 2 + 1] = __floats2half2_rn(acc.z, acc.w);
        float4 a = s_as[lane], b = s_ad[lane];
        float ps = acc.x * a.x + acc.y * a.y + acc.z * a.z + acc.w * a.w;
        float pd = acc.x * b.x + acc.y * b.y + acc.z * b.z + acc.w * b.w;
        #pragma unroll
        for (int o = 4; o > 0; o >>= 1) {
            ps += __shfl_down_sync(0xFFFFFFFFu, ps, o, 8);
            pd += __shfl_down_sync(0xFFFFFFFFu, pd, o, 8);
        }
        if ((lane & 7) == 0) {
            int h = lane >> 3;
            g_asrc[n * HH + h] = ps;
            g_adst[n * HH + h] = pd;
        }
    }
}

// ================= hidden GEMM (TF32 mma, double-buffered) + alpha ==========
#define HS_STRIDE 20
#define WS_STRIDE 136
__global__ __launch_bounds__(256) void gemmH_mma_kernel(
    const float* __restrict__ Wg,
    const float* __restrict__ a_src, const float* __restrict__ a_dst)
{
    __shared__ unsigned Hs[2][128 * HS_STRIDE];
    __shared__ unsigned Wsm[2][16 * WS_STRIDE];
    __shared__ float sA[DD], sB[DD];

    int t = threadIdx.x;
    int lane = t & 31;
    int w = t >> 5;
    int gid = lane >> 2;
    int tg = lane & 3;
    int n0 = blockIdx.x * 128;
    int m0 = w * 16;

    if (t < DD) { sA[t] = a_src[t]; sB[t] = a_dst[t]; }

    float acc[16][4];
    #pragma unroll
    for (int nt = 0; nt < 16; nt++)
        #pragma unroll
        for (int q = 0; q < 4; q++) acc[nt][q] = 0.0f;

    auto load_tile = [&](int kt, int buf) {
        #pragma unroll
        for (int it = 0; it < 2; it++) {
            int idx = t + it * 256;
            int r = idx >> 2, q = idx & 3;
            float4 v = {0, 0, 0, 0};
            if (n0 + r < NN) v = ((const float4*)g_h)[(size_t)(n0 + r) * 32 + kt * 4 + q];
            unsigned* p = &Hs[buf][r * HS_STRIDE + q * 4];
            p[0] = f2tf32(v.x); p[1] = f2tf32(v.y); p[2] = f2tf32(v.z); p[3] = f2tf32(v.w);
        }
        #pragma unroll
        for (int it = 0; it < 2; it++) {
            int idx = t + it * 256;
            int r = idx >> 5, q = idx & 31;
            float4 v = ((const float4*)Wg)[(kt * 16 + r) * 32 + q];
            unsigned* p = &Wsm[buf][r * WS_STRIDE + q * 4];
            p[0] = f2tf32(v.x); p[1] = f2tf32(v.y); p[2] = f2tf32(v.z); p[3] = f2tf32(v.w);
        }
    };

    load_tile(0, 0);
    __syncthreads();

    for (int kt = 0; kt < 8; kt++) {
        int cur = kt & 1;
        if (kt < 7) load_tile(kt + 1, cur ^ 1);

        #pragma unroll
        for (int kk = 0; kk < 2; kk++) {
            unsigned a0 = Hs[cur][(m0 + gid) * HS_STRIDE + kk * 8 + tg];
            unsigned a1 = Hs[cur][(m0 + gid + 8) * HS_STRIDE + kk * 8 + tg];
            unsigned a2 = Hs[cur][(m0 + gid) * HS_STRIDE + kk * 8 + tg + 4];
            unsigned a3 = Hs[cur][(m0 + gid + 8) * HS_STRIDE + kk * 8 + tg + 4];
            #pragma unroll
            for (int nt = 0; nt < 16; nt++) {
                unsigned b0 = Wsm[cur][(kk * 8 + tg) * WS_STRIDE + nt * 8 + gid];
                unsigned b1 = Wsm[cur][(kk * 8 + tg + 4) * WS_STRIDE + nt * 8 + gid];
                asm volatile(
                    "mma.sync.aligned.m16n8k8.row.col.f32.tf32.tf32.f32 "
                    "{%0,%1,%2,%3}, {%4,%5,%6,%7}, {%8,%9}, {%0,%1,%2,%3};"
                    : "+f"(acc[nt][0]), "+f"(acc[nt][1]), "+f"(acc[nt][2]), "+f"(acc[nt][3])
                    : "r"(a0), "r"(a1), "r"(a2), "r"(a3), "r"(b0), "r"(b1));
            }
        }
        __syncthreads();
    }

    int na = n0 + m0 + gid;
    int nb = na + 8;
    #pragma unroll
    for (int nt = 0; nt < 16; nt++) {
        if (na < NN) ((__half2*)g_hp)[(size_t)na * 64 + nt * 4 + tg] = __floats2half2_rn(acc[nt][0], acc[nt][1]);
        if (nb < NN) ((__half2*)g_hp)[(size_t)nb * 64 + nt * 4 + tg] = __floats2half2_rn(acc[nt][2], acc[nt][3]);
    }
    float psa[4] = {0, 0, 0, 0}, pda[4] = {0, 0, 0, 0};
    float psb[4] = {0, 0, 0, 0}, pdb[4] = {0, 0, 0, 0};
    #pragma unroll
    for (int nt = 0; nt < 16; nt++) {
        int h = nt >> 2;
        int ch = nt * 8 + 2 * tg;
        float s0 = sA[ch], s1 = sA[ch + 1];
        float d0 = sB[ch], d1 = sB[ch + 1];
        psa[h] += acc[nt][0] * s0 + acc[nt][1] * s1;
        pda[h] += acc[nt][0] * d0 + acc[nt][1] * d1;
        psb[h] += acc[nt][2] * s0 + acc[nt][3] * s1;
        pdb[h] += acc[nt][2] * d0 + acc[nt][3] * d1;
    }
    #pragma unroll
    for (int h = 0; h < 4; h++) {
        #pragma unroll
        for (int o = 1; o < 4; o <<= 1) {
            psa[h] += __shfl_xor_sync(0xFFFFFFFFu, psa[h], o);
            pda[h] += __shfl_xor_sync(0xFFFFFFFFu, pda[h], o);
            psb[h] += __shfl_xor_sync(0xFFFFFFFFu, psb[h], o);
            pdb[h] += __shfl_xor_sync(0xFFFFFFFFu, pdb[h], o);
        }
    }
    if (tg == 0) {
        if (na < NN) {
            float4 v = {psa[0], psa[1], psa[2], psa[3]};
            ((float4*)g_asrc)[na] = v;
            float4 u = {pda[0], pda[1], pda[2], pda[3]};
            ((float4*)g_adst)[na] = u;
        }
        if (nb < NN) {
            float4 v = {psb[0], psb[1], psb[2], psb[3]};
            ((float4*)g_asrc)[nb] = v;
            float4 u = {pdb[0], pdb[1], pdb[2], pdb[3]};
            ((float4*)g_adst)[nb] = u;
        }
    }
}

// ================= fused one-pass edge aggregation + LN + ELU + residual ====
// warp per dst node; lane owns channels [lane*4, lane*4+4); head = lane>>3.
// Full chunks take the unrolled path (8 gathers in flight).
__global__ __launch_bounds__(256) void fused_edge_kernel(
    const float* __restrict__ bias,
    const float* __restrict__ lng, const float* __restrict__ lnb,
    int is_first, int is_last, float* __restrict__ outp)
{
    int lane = threadIdx.x & 31;
    int h = lane >> 3;
    int wid = (blockIdx.x * blockDim.x + threadIdx.x) >> 5;
    int tw = (gridDim.x * blockDim.x) >> 5;
    int grp = lane & 24;
    int j8 = lane & 7;
    const uint2* hp2 = (const uint2*)g_hp;

    for (int d = wid; d < NN; d += tw) {
        int beg = g_off[d], end = g_off[d + 1];
        float4 ad4 = ((const float4*)g_adst)[d];
        float adh = (h == 0) ? ad4.x : (h == 1) ? ad4.y : (h == 2) ? ad4.z : ad4.w;

        int i0 = beg + j8;
        int s_cur = 0; float as_cur = 0.0f;
        if (i0 < end) {
            s_cur = __ldg(&g_csr[i0]);
            as_cur = __ldg(&g_asrc[s_cur * HH + h]);
        }

        float z = 0.0f;
        float4 acc = {0, 0, 0, 0};
        int c = beg;
        for (; c + 8 <= end; c += 8) {
            int inx = c + 8 + j8;
            int s_nxt = 0; float as_nxt = 0.0f;
            if (inx < end) {
                s_nxt = __ldg(&g_csr[inx]);
                as_nxt = __ldg(&g_asrc[s_nxt * HH + h]);
            }
            float e_own = __expf(fminf(lrelu(as_cur + adh), 60.0f));
            z += e_own;
            #pragma unroll
            for (int j = 0; j < 8; j++) {
                int sj   = __shfl_sync(0xFFFFFFFFu, s_cur, grp | j);
                float ej = __shfl_sync(0xFFFFFFFFu, e_own, grp | j);
                uint2 hv = __ldg(&hp2[(size_t)sj * 32 + lane]);
                float2 f01 = __half22float2(*reinterpret_cast<const __half2*>(&hv.x));
                float2 f23 = __half22float2(*reinterpret_cast<const __half2*>(&hv.y));
                acc.x += ej * f01.x;
                acc.y += ej * f01.y;
                acc.z += ej * f23.x;
                acc.w += ej * f23.y;
            }
            s_cur = s_nxt; as_cur = as_nxt;
        }
        int lim = end - c;
        if (lim > 0) {
            float e_own = 0.0f;
            if (j8 < lim) e_own = __expf(fminf(lrelu(as_cur + adh), 60.0f));
            z += e_own;
            for (int j = 0; j < lim; j++) {
                int sj   = __shfl_sync(0xFFFFFFFFu, s_cur, grp | j);
                float ej = __shfl_sync(0xFFFFFFFFu, e_own, grp | j);
                uint2 hv = __ldg(&hp2[(size_t)sj * 32 + lane]);
                float2 f01 = __half22float2(*reinterpret_cast<const __half2*>(&hv.x));
                float2 f23 = __half22float2(*reinterpret_cast<const __half2*>(&hv.y));
                acc.x += ej * f01.x;
                acc.y += ej * f01.y;
                acc.z += ej * f23.x;
                acc.w += ej * f23.y;
            }
        }

        #pragma unroll
        for (int o = 4; o > 0; o >>= 1) z += __shfl_xor_sync(0xFFFFFFFFu, z, o, 8);
        float inv = 1.0f / (z + 1e-16f);

        float4 b4 = ((const float4*)bias)[lane];
        float4 v;
        v.x = acc.x * inv + b4.x;
        v.y = acc.y * inv + b4.y;
        v.z = acc.z * inv + b4.z;
        v.w = acc.w * inv + b4.w;

        float s  = v.x + v.y + v.z + v.w;
        float sq = v.x * v.x + v.y * v.y + v.z * v.z + v.w * v.w;
        #pragma unroll
        for (int o = 16; o > 0; o >>= 1) {
            s  += __shfl_xor_sync(0xFFFFFFFFu, s, o);
            sq += __shfl_xor_sync(0xFFFFFFFFu, sq, o);
        }
        float mu = s * (1.0f / 128.0f);
        float var = sq * (1.0f / 128.0f) - mu * mu;
        float rs = rsqrtf(var + 1e-5f);
        float4 gv = ((const float4*)lng)[lane];
        float4 bv = ((const float4*)lnb)[lane];
        float4 r;
        r.x = elu((v.x - mu) * rs * gv.x + bv.x);
        r.y = elu((v.y - mu) * rs * gv.y + bv.y);
        r.z = elu((v.z - mu) * rs * gv.z + bv.z);
        r.w = elu((v.w - mu) * rs * gv.w + bv.w);
        if (!is_first) {
            float4 hold = ((const float4*)g_h)[(size_t)d * 32 + lane];
            r.x += hold.x; r.y += hold.y; r.z += hold.z; r.w += hold.w;
        }
        ((float4*)g_h)[(size_t)d * 32 + lane] = r;
        if (is_last) ((float4*)outp)[(size_t)d * 32 + lane] = r;
    }
}

// ================= graph pooling (counts folded into acc) =================
#define NPB 32
__global__ void pool_acc_kernel(const int* __restrict__ batch) {
    int j = threadIdx.x;
    int n0 = blockIdx.x * NPB;
    int n1 = n0 + NPB; if (n1 > NN) n1 = NN;
    if (n0 >= NN) return;
    int gcur = batch[n0];
    float acc = 0.0f;
    int cnt = 0;
    for (int n = n0; n < n1; n++) {
        int g = batch[n];
        if (g != gcur) {
            atomicAdd(&g_gsum[gcur * DD + j], acc);
            if (j == 0) atomicAdd(&g_gcnt[gcur], (float)cnt);
            acc = 0.0f;
            cnt = 0;
            gcur = g;
        }
        acc += g_h[(size_t)n * DD + j];
        cnt++;
    }
    atomicAdd(&g_gsum[gcur * DD + j], acc);
    if (j == 0) atomicAdd(&g_gcnt[gcur], (float)cnt);
}

__global__ void pool_fin_kernel(float* __restrict__ outp) {
    int i = blockIdx.x * blockDim.x + threadIdx.x;
    if (i < GG * DD) {
        int g = i >> 7;
        outp[NN * DD + i] = g_gsum[i] / fmaxf(g_gcnt[g], 1.0f);
    }
}

// ================= launch =================
extern "C" void kernel_launch(void* const* d_in, const int* in_sizes, int n_in,
                              void* d_out, int out_size) {
    const float* x      = (const float*)d_in[0];
    const int*   ei     = (const int*)  d_in[1];
    const int*   batch  = (const int*)  d_in[2];
    const float* W0     = (const float*)d_in[3];
    const float* a_src0 = (const float*)d_in[4];
    const float* a_dst0 = (const float*)d_in[5];
    const float* b0     = (const float*)d_in[6];
    const float* Ws     = (const float*)d_in[7];
    const float* a_srcs = (const float*)d_in[8];
    const float* a_dsts = (const float*)d_in[9];
    const float* bs     = (const float*)d_in[10];
    const float* ln_g   = (const float*)d_in[11];
    const float* ln_b   = (const float*)d_in[12];
    float* out = (float*)d_out;

    const int* srcp = ei;
    const int* dstp = ei + EE;

    void* p_cnt = nullptr;  cudaGetSymbolAddress(&p_cnt,  g_cnt);
    void* p_gsum = nullptr; cudaGetSymbolAddress(&p_gsum, g_gsum);
    void* p_gcnt = nullptr; cudaGetSymbolAddress(&p_gcnt, g_gcnt);
    cudaMemsetAsync(p_cnt, 0, NN * sizeof(int));
    cudaMemsetAsync(p_gsum, 0, GG * DD * sizeof(float));
    cudaMemsetAsync(p_gcnt, 0, GG * sizeof(float));

    int csr_threads = (EP + 3) / 4;
    csr_hist_kernel<<<(csr_threads + 255) / 256, 256>>>(dstp);
    csr_scan_kernel<<<1, 1024>>>();
    csr_scatter_kernel<<<(csr_threads + 255) / 256, 256>>>(srcp, dstp);

    for (int l = 0; l < LL; l++) {
        const float* asr  = (l == 0) ? a_src0 : (a_srcs + (l - 1) * HH * CC);
        const float* ads  = (l == 0) ? a_dst0 : (a_dsts + (l - 1) * HH * CC);
        const float* bias = (l == 0) ? b0     : (bs + (l - 1) * DD);

        if (l == 0)
            gemm0_kernel<<<2048, 256>>>(x, W0, asr, ads);
        else
            gemmH_mma_kernel<<<(NN + 127) / 128, 256>>>(Ws + (l - 1) * DD * DD, asr, ads);

        fused_edge_kernel<<<2048, 256>>>(bias, ln_g + l * DD, ln_b + l * DD,
                                         (l == 0) ? 1 : 0, (l == LL - 1) ? 1 : 0, out);
    }

    pool_acc_kernel<<<(NN + NPB - 1) / NPB, 128>>>(batch);
    pool_fin_kernel<<<(GG * DD + 255) / 256, 256>>>(out);
}